// round 2
// baseline (speedup 1.0000x reference)
#include <cuda_runtime.h>
#include <math_constants.h>

// Problem: x [B=64, C=512, H=28, W=28] fp32, cc [B,28,28] bool widened to int32.
// out [B, 2C]: out[b, c]      = (sum_{hw} x[b,c,hw]*cc[b,hw] + x[b,c,0]) / max(cnt_b, 1)
//              out[b, C + c]  = max_{hw} x[b,c,hw]
//
// One CTA per (b,c) row: 784 contiguous floats = 196 float4 loads.
// Mask row = 784 int32 = 196 int4 loads (L2-resident, reused 512x per batch).

#define HW 784
#define HW4 196
#define C_DIM 512
#define THREADS 128

__global__ __launch_bounds__(THREADS) void pool_kernel(
    const float* __restrict__ x,
    const int* __restrict__ cc,
    float* __restrict__ out)
{
    const int bc = blockIdx.x;          // 0 .. B*C-1
    const int b  = bc >> 9;             // / 512
    const int c  = bc & (C_DIM - 1);

    const float4* __restrict__ xr = reinterpret_cast<const float4*>(x + (size_t)bc * HW);
    const int4*   __restrict__ mr = reinterpret_cast<const int4*>(cc + (size_t)b * HW);

    float sum = 0.0f;
    float cnt = 0.0f;
    float mx  = -CUDART_INF_F;

    const int tid = threadIdx.x;
    #pragma unroll 2
    for (int i = tid; i < HW4; i += THREADS) {
        float4 v = xr[i];
        int4   m = mr[i];
        sum += (m.x ? v.x : 0.0f) + (m.y ? v.y : 0.0f)
             + (m.z ? v.z : 0.0f) + (m.w ? v.w : 0.0f);
        cnt += (float)(m.x + m.y + m.z + m.w);
        mx = fmaxf(mx, fmaxf(fmaxf(v.x, v.y), fmaxf(v.z, v.w)));
    }

    // warp reduce
    #pragma unroll
    for (int off = 16; off > 0; off >>= 1) {
        sum += __shfl_down_sync(0xffffffffu, sum, off);
        cnt += __shfl_down_sync(0xffffffffu, cnt, off);
        mx   = fmaxf(mx, __shfl_down_sync(0xffffffffu, mx, off));
    }

    __shared__ float s_sum[4], s_cnt[4], s_max[4];
    const int wid = tid >> 5;
    const int lid = tid & 31;
    if (lid == 0) { s_sum[wid] = sum; s_cnt[wid] = cnt; s_max[wid] = mx; }
    __syncthreads();

    if (tid == 0) {
        float fsum = s_sum[0] + s_sum[1] + s_sum[2] + s_sum[3];
        float fcnt = s_cnt[0] + s_cnt[1] + s_cnt[2] + s_cnt[3];
        float fmx  = fmaxf(fmaxf(s_max[0], s_max[1]), fmaxf(s_max[2], s_max[3]));

        // reference quirk: masked_sum gets an extra + x[b,c,0,0]
        fsum += x[(size_t)bc * HW];   // L1 hit (we just loaded this line)
        float denom = (fcnt == 0.0f) ? 1.0f : fcnt;

        out[(size_t)b * (2 * C_DIM) + c]          = fsum / denom;
        out[(size_t)b * (2 * C_DIM) + C_DIM + c]  = fmx;
    }
}

extern "C" void kernel_launch(void* const* d_in, const int* in_sizes, int n_in,
                              void* d_out, int out_size)
{
    const float* x  = (const float*)d_in[0];
    const int*   cc = (const int*)d_in[1];
    float*       o  = (float*)d_out;

    // grid = B*C = 64*512 = 32768 CTAs
    pool_kernel<<<64 * C_DIM, THREADS>>>(x, cc, o);
}

// round 3
// speedup vs baseline: 1.4983x; 1.4983x over previous
#include <cuda_runtime.h>
#include <math_constants.h>

// x [B=64, C=512, H=28, W=28] fp32; cc [B,28,28] bool widened to int32.
// out [B, 2C]: out[b,c]     = (sum_hw x[b,c,hw]*cc[b,hw] + x[b,c,0]) / max(cnt_b,1)
//              out[b,C+c]   = max_hw x[b,c,hw]
//
// CTA = 8 consecutive channels of one batch (grid 4096, 256 threads).
// Phase 1: convert batch mask -> smem float mask, block-reduce count (once per CTA).
// Phase 2: warp-per-row stream: 6-7 float4 LDGs/lane + smem mask FFMA, warp reduce.

#define HW   784
#define HW4  196
#define C_DIM 512
#define THREADS 256
#define ROWS_PER_CTA 8

__global__ __launch_bounds__(THREADS) void pool_kernel(
    const float* __restrict__ x,
    const int* __restrict__ cc,
    float* __restrict__ out)
{
    __shared__ float s_m[HW];      // float mask for this batch
    __shared__ float s_red[8];
    __shared__ float s_denom;

    const int tid  = threadIdx.x;
    const int wid  = tid >> 5;
    const int lane = tid & 31;

    const int bc0 = blockIdx.x * ROWS_PER_CTA;   // first row of this CTA
    const int b   = bc0 >> 9;                    // all 8 rows share this batch

    // ---- Phase 1: mask -> smem float, count once per CTA ----
    const int4* __restrict__ mr = reinterpret_cast<const int4*>(cc + (size_t)b * HW);
    float cnt = 0.0f;
    for (int i = tid; i < HW4; i += THREADS) {   // single iter for tid<196
        int4 m = mr[i];
        float4 f;
        f.x = m.x ? 1.0f : 0.0f;
        f.y = m.y ? 1.0f : 0.0f;
        f.z = m.z ? 1.0f : 0.0f;
        f.w = m.w ? 1.0f : 0.0f;
        *reinterpret_cast<float4*>(&s_m[4 * i]) = f;
        cnt += (f.x + f.y) + (f.z + f.w);
    }
    #pragma unroll
    for (int off = 16; off > 0; off >>= 1)
        cnt += __shfl_down_sync(0xffffffffu, cnt, off);
    if (lane == 0) s_red[wid] = cnt;
    __syncthreads();
    if (tid == 0) {
        float c = 0.0f;
        #pragma unroll
        for (int k = 0; k < 8; k++) c += s_red[k];
        s_denom = (c == 0.0f) ? 1.0f : c;
    }
    __syncthreads();

    // ---- Phase 2: warp-per-row ----
    const int bc = bc0 + wid;
    const float4* __restrict__ xr = reinterpret_cast<const float4*>(x + (size_t)bc * HW);
    const float4* __restrict__ mm = reinterpret_cast<const float4*>(s_m);

    float sum0 = 0.0f, sum1 = 0.0f;
    float mx   = -CUDART_INF_F;

    // 196 float4 groups: 6 full strides of 32, then 4-wide tail
    #pragma unroll
    for (int j = 0; j < 6; j++) {
        const int i = lane + 32 * j;
        float4 v = xr[i];
        float4 f = mm[i];
        sum0 = fmaf(v.x, f.x, fmaf(v.y, f.y, sum0));
        sum1 = fmaf(v.z, f.z, fmaf(v.w, f.w, sum1));
        mx = fmaxf(mx, fmaxf(fmaxf(v.x, v.y), fmaxf(v.z, v.w)));
    }
    if (lane < 4) {
        const int i = lane + 192;
        float4 v = xr[i];
        float4 f = mm[i];
        sum0 = fmaf(v.x, f.x, fmaf(v.y, f.y, sum0));
        sum1 = fmaf(v.z, f.z, fmaf(v.w, f.w, sum1));
        mx = fmaxf(mx, fmaxf(fmaxf(v.x, v.y), fmaxf(v.z, v.w)));
    }

    float sum = sum0 + sum1;
    #pragma unroll
    for (int off = 16; off > 0; off >>= 1) {
        sum += __shfl_down_sync(0xffffffffu, sum, off);
        mx   = fmaxf(mx, __shfl_down_sync(0xffffffffu, mx, off));
    }

    if (lane == 0) {
        const int c = bc & (C_DIM - 1);
        // reference quirk: masked_sum gets an extra + x[b,c,0,0] (L1 hit)
        sum += x[(size_t)bc * HW];
        out[(size_t)b * (2 * C_DIM) + c]         = sum / s_denom;
        out[(size_t)b * (2 * C_DIM) + C_DIM + c] = mx;
    }
}

extern "C" void kernel_launch(void* const* d_in, const int* in_sizes, int n_in,
                              void* d_out, int out_size)
{
    const float* x  = (const float*)d_in[0];
    const int*   cc = (const int*)d_in[1];
    float*       o  = (float*)d_out;

    // grid = B*C / ROWS_PER_CTA = 32768 / 8 = 4096 CTAs
    pool_kernel<<<(64 * C_DIM) / ROWS_PER_CTA, THREADS>>>(x, cc, o);
}